// round 13
// baseline (speedup 1.0000x reference)
#include <cuda_runtime.h>
#include <cuda_bf16.h>
#include <math.h>

// Problem constants (match reference_code)
#define NU      100000
#define NI      50000
#define NN      (NU + NI)          // 150000 nodes
#define EK      64
#define FEATN   1024
#define NE      3000000            // undirected (bipartite) edges
#define NDIR    (2 * NE)           // 6,000,000 directed CSR entries
#define BATCHN  16384
#define NKF     (NN * EK)          // 9,600,000 elems per node-embedding buffer
#define NCHUNK  ((NN + 1023) / 1024)   // 147 scan chunks

// ---------------- scratch (static device globals; no runtime allocation) ---
__device__ __nv_bfloat16 g_x0h[NKF];       // x0 bf16 (gather source, layer 0)
__device__ __nv_bfloat16 g_x1h[NKF];       // x1 bf16 (gather source, layer 1)
__device__ __nv_bfloat16 g_x2h[NKF];       // x2 bf16 (gather source, layer 3-at-batch)
__device__ float g_x1f[NKF];               // x1 fp32 (own-row read at batch nodes)
__device__ float g_x2f[NKF];               // x2 fp32 (own-row read at batch nodes)
__device__ int   g_deg[NN];
__device__ float g_dinv[NN];
__device__ int   g_offs[NN + 1];
__device__ int   g_cur[NN];
__device__ int   g_bsum[NCHUNK];
__device__ int2  g_csr[NDIR];              // .x = src node, .y = bitcast(fp32 norm)
__device__ float g_gamma[2 * BATCHN * EK]; // [0..B): user rows, [B..2B): item rows
__device__ float g_proj[BATCHN * EK];

// ---------------- degree ----------------
__global__ void k_zero_deg() {
    int i = blockIdx.x * blockDim.x + threadIdx.x;
    if (i < NN) g_deg[i] = 0;
}

__global__ void k_count(const int* __restrict__ ue, const int* __restrict__ ie) {
    int e = blockIdx.x * blockDim.x + threadIdx.x;
    if (e < NE) {
        atomicAdd(&g_deg[ue[e]], 1);
        atomicAdd(&g_deg[NU + ie[e]], 1);
    }
}

// ---------------- prefix scan over degrees -> CSR offsets -----------------
__global__ void k_blocksum() {
    __shared__ int ws[32];
    int i = blockIdx.x * 1024 + threadIdx.x;
    int v = (i < NN) ? g_deg[i] : 0;
    #pragma unroll
    for (int o = 16; o > 0; o >>= 1) v += __shfl_down_sync(0xffffffff, v, o);
    if ((threadIdx.x & 31) == 0) ws[threadIdx.x >> 5] = v;
    __syncthreads();
    if (threadIdx.x < 32) {
        int t = ws[threadIdx.x];
        #pragma unroll
        for (int o = 16; o > 0; o >>= 1) t += __shfl_down_sync(0xffffffff, t, o);
        if (threadIdx.x == 0) g_bsum[blockIdx.x] = t;
    }
}

__global__ void k_scanbsum() {   // tiny serial scan, 147 elements
    if (threadIdx.x == 0) {
        int c = 0;
        for (int i = 0; i < NCHUNK; i++) { int t = g_bsum[i]; g_bsum[i] = c; c += t; }
    }
}

__global__ void k_localscan() {  // also computes dinv (fused, saves a launch)
    __shared__ int ws[32];
    int i = blockIdx.x * 1024 + threadIdx.x;
    int v = (i < NN) ? g_deg[i] : 0;
    int lane = threadIdx.x & 31, w = threadIdx.x >> 5;
    int s = v;
    #pragma unroll
    for (int o = 1; o < 32; o <<= 1) {
        int t = __shfl_up_sync(0xffffffff, s, o);
        if (lane >= o) s += t;
    }
    if (lane == 31) ws[w] = s;
    __syncthreads();
    if (w == 0) {
        int t = ws[lane];
        int ss = t;
        #pragma unroll
        for (int o = 1; o < 32; o <<= 1) {
            int q = __shfl_up_sync(0xffffffff, ss, o);
            if (lane >= o) ss += q;
        }
        ws[lane] = ss - t;   // exclusive
    }
    __syncthreads();
    int excl = (s - v) + ws[w] + g_bsum[blockIdx.x];
    if (i < NN) {
        g_offs[i] = excl;
        g_cur[i]  = excl;
        g_dinv[i] = (v > 0) ? rsqrtf((float)v) : 0.0f;
    }
    if (i == 0) g_offs[NN] = NDIR;
}

// ---------------- fill CSR (src id + edge norm packed) --------------------
__global__ void k_fill(const int* __restrict__ ue, const int* __restrict__ ie) {
    int e = blockIdx.x * blockDim.x + threadIdx.x;
    if (e >= NE) return;
    int u  = ue[e];
    int it = NU + ie[e];
    float nrm = g_dinv[u] * g_dinv[it];
    int nb = __float_as_int(nrm);
    int pu = atomicAdd(&g_cur[u], 1);
    g_csr[pu] = make_int2(it, nb);
    int pi = atomicAdd(&g_cur[it], 1);
    g_csr[pi] = make_int2(u, nb);
}

// ---------------- init: x0h = bf16(concat(Gu, Gi)) ----------------
__global__ void k_init(const float* __restrict__ Gu, const float* __restrict__ Gi) {
    int i = blockIdx.x * blockDim.x + threadIdx.x;   // float4 index
    const int n4 = NKF / 4;
    if (i < n4) {
        const int gu4 = (NU * EK) / 4;
        float4 v = (i < gu4) ? ((const float4*)Gu)[i]
                             : ((const float4*)Gi)[i - gu4];
        __nv_bfloat162 h0 = __float22bfloat162_rn(make_float2(v.x, v.y));
        __nv_bfloat162 h1 = __float22bfloat162_rn(make_float2(v.z, v.w));
        ((__nv_bfloat162*)g_x0h)[i * 2 + 0] = h0;
        ((__nv_bfloat162*)g_x0h)[i * 2 + 1] = h1;
    }
}

// ---------------- pull-gather layer: one warp per destination node --------
// bf16 source rows (128 B/row), fp32 accumulation. Writes bf16 (for the next
// gather) and fp32 (for own-row reads at batch nodes).
__global__ void k_gather(int layer) {
    const __nv_bfloat162* __restrict__ X =
        (const __nv_bfloat162*)(layer ? g_x1h : g_x0h);
    __nv_bfloat162* __restrict__ Yh = (__nv_bfloat162*)(layer ? g_x2h : g_x1h);
    float*          __restrict__ Yf = layer ? g_x2f : g_x1f;

    int node = (blockIdx.x * blockDim.x + threadIdx.x) >> 5;
    if (node >= NN) return;
    int lane = threadIdx.x & 31;

    int beg = g_offs[node];
    int end = g_offs[node + 1];

    float2 s = make_float2(0.f, 0.f);
    int j = beg;
    for (; j + 4 <= end; j += 4) {
        int2 c0 = g_csr[j];
        int2 c1 = g_csr[j + 1];
        int2 c2 = g_csr[j + 2];
        int2 c3 = g_csr[j + 3];
        float2 v0 = __bfloat1622float2(X[(size_t)c0.x * (EK / 2) + lane]);
        float2 v1 = __bfloat1622float2(X[(size_t)c1.x * (EK / 2) + lane]);
        float2 v2 = __bfloat1622float2(X[(size_t)c2.x * (EK / 2) + lane]);
        float2 v3 = __bfloat1622float2(X[(size_t)c3.x * (EK / 2) + lane]);
        float n0 = __int_as_float(c0.y), n1 = __int_as_float(c1.y);
        float n2 = __int_as_float(c2.y), n3 = __int_as_float(c3.y);
        s.x += v0.x * n0 + v1.x * n1 + v2.x * n2 + v3.x * n3;
        s.y += v0.y * n0 + v1.y * n1 + v2.y * n2 + v3.y * n3;
    }
    for (; j < end; j++) {
        int2 c = g_csr[j];
        float2 v = __bfloat1622float2(X[(size_t)c.x * (EK / 2) + lane]);
        float n = __int_as_float(c.y);
        s.x += v.x * n;
        s.y += v.y * n;
    }

    Yh[(size_t)node * (EK / 2) + lane] = __float22bfloat162_rn(s);
    *(float2*)(Yf + (size_t)node * EK + lane * 2) = s;
}

// ---------------- layer 3 + accumulate, only at batch rows ----------------
// One warp per batch slot (32768 slots: users then items). Gathers x3 from
// x2(bf16) and writes gamma = x0 + x1 + x2 + x3 (own-row terms in fp32).
__global__ void k_gather3(const float* __restrict__ Gu, const float* __restrict__ Gi,
                          const int* __restrict__ users, const int* __restrict__ items) {
    int w = (blockIdx.x * blockDim.x + threadIdx.x) >> 5;
    if (w >= 2 * BATCHN) return;
    int lane = threadIdx.x & 31;

    int node = (w < BATCHN) ? users[w] : NU + items[w - BATCHN];

    int beg = g_offs[node];
    int end = g_offs[node + 1];
    const __nv_bfloat162* __restrict__ X = (const __nv_bfloat162*)g_x2h;

    float2 s = make_float2(0.f, 0.f);
    int j = beg;
    for (; j + 4 <= end; j += 4) {
        int2 c0 = g_csr[j];
        int2 c1 = g_csr[j + 1];
        int2 c2 = g_csr[j + 2];
        int2 c3 = g_csr[j + 3];
        float2 v0 = __bfloat1622float2(X[(size_t)c0.x * (EK / 2) + lane]);
        float2 v1 = __bfloat1622float2(X[(size_t)c1.x * (EK / 2) + lane]);
        float2 v2 = __bfloat1622float2(X[(size_t)c2.x * (EK / 2) + lane]);
        float2 v3 = __bfloat1622float2(X[(size_t)c3.x * (EK / 2) + lane]);
        float n0 = __int_as_float(c0.y), n1 = __int_as_float(c1.y);
        float n2 = __int_as_float(c2.y), n3 = __int_as_float(c3.y);
        s.x += v0.x * n0 + v1.x * n1 + v2.x * n2 + v3.x * n3;
        s.y += v0.y * n0 + v1.y * n1 + v2.y * n2 + v3.y * n3;
    }
    for (; j < end; j++) {
        int2 c = g_csr[j];
        float2 v = __bfloat1622float2(X[(size_t)c.x * (EK / 2) + lane]);
        float n = __int_as_float(c.y);
        s.x += v.x * n;
        s.y += v.y * n;
    }

    size_t off = (size_t)node * EK + lane * 2;
    const float* x0p = (node < NU) ? (Gu + off) : (Gi + off - (size_t)NU * EK);
    float2 a0 = *(const float2*)x0p;
    float2 a1 = *(const float2*)(g_x1f + off);
    float2 a2 = *(const float2*)(g_x2f + off);
    float2 g;
    g.x = a0.x + a1.x + a2.x + s.x;
    g.y = a0.y + a1.y + a2.y + s.y;
    *(float2*)(g_gamma + (size_t)w * EK + lane * 2) = g;
}

// ---------------- projection GEMM: proj[b][k] = F[items[b]] . proj_w[k] + bias[k]
__global__ void k_proj_gemm(const float* __restrict__ F, const float* __restrict__ W,
                            const float* __restrict__ bias, const int* __restrict__ items) {
    __shared__ float As[64][68];
    __shared__ float Ws[64][68];
    __shared__ int   ids[64];

    int b0 = blockIdx.x * 64;
    int t  = threadIdx.x;           // 0..255
    if (t < 64) ids[t] = items[b0 + t];
    __syncthreads();

    float c[4][4];
    #pragma unroll
    for (int r = 0; r < 4; r++)
        #pragma unroll
        for (int q = 0; q < 4; q++) c[r][q] = 0.f;

    int ty = t >> 4;     // 0..15
    int tx = t & 15;     // 0..15

    for (int kk = 0; kk < FEATN; kk += 64) {
        #pragma unroll
        for (int i = 0; i < 4; i++) {
            int idx = t + i * 256;       // 0..1023
            int row = idx >> 4;          // 0..63
            int q   = idx & 15;          // float4 slot
            float4 a = *(const float4*)(F + (size_t)ids[row] * FEATN + kk + q * 4);
            As[row][q * 4 + 0] = a.x; As[row][q * 4 + 1] = a.y;
            As[row][q * 4 + 2] = a.z; As[row][q * 4 + 3] = a.w;
            float4 w = *(const float4*)(W + (size_t)row * FEATN + kk + q * 4);
            Ws[row][q * 4 + 0] = w.x; Ws[row][q * 4 + 1] = w.y;
            Ws[row][q * 4 + 2] = w.z; Ws[row][q * 4 + 3] = w.w;
        }
        __syncthreads();

        #pragma unroll 16
        for (int j = 0; j < 64; j++) {
            float a[4], b[4];
            #pragma unroll
            for (int r = 0; r < 4; r++) a[r] = As[ty * 4 + r][j];
            #pragma unroll
            for (int q = 0; q < 4; q++) b[q] = Ws[tx * 4 + q][j];
            #pragma unroll
            for (int r = 0; r < 4; r++)
                #pragma unroll
                for (int q = 0; q < 4; q++) c[r][q] += a[r] * b[q];
        }
        __syncthreads();
    }

    #pragma unroll
    for (int r = 0; r < 4; r++)
        #pragma unroll
        for (int q = 0; q < 4; q++)
            g_proj[(size_t)(b0 + ty * 4 + r) * EK + tx * 4 + q] = c[r][q] + bias[tx * 4 + q];
}

// ---------------- final scoring: warp per batch element ----------------
__global__ void k_score(const float* __restrict__ Tu, const int* __restrict__ users,
                        float* __restrict__ out) {
    int b = (blockIdx.x * blockDim.x + threadIdx.x) >> 5;
    if (b >= BATCHN) return;
    int lane = threadIdx.x & 31;

    int u = users[b];

    float2 au = *(const float2*)(g_gamma + (size_t)b * EK + lane * 2);
    float2 ai = *(const float2*)(g_gamma + (size_t)(BATCHN + b) * EK + lane * 2);
    float2 p  = *(const float2*)(g_proj + (size_t)b * EK + lane * 2);
    float2 tv = *(const float2*)(Tu + (size_t)u * EK + lane * 2);

    float gdot = au.x * ai.x + au.y * ai.y;     // (acc_u . acc_i); /16 later
    float ns   = p.x * p.x + p.y * p.y;         // ||proj||^2
    float tp   = tv.x * p.x + tv.y * p.y;       // theta . proj

    #pragma unroll
    for (int o = 16; o > 0; o >>= 1) {
        gdot += __shfl_down_sync(0xffffffff, gdot, o);
        ns   += __shfl_down_sync(0xffffffff, ns,   o);
        tp   += __shfl_down_sync(0xffffffff, tp,   o);
    }
    if (lane == 0)
        out[b] = gdot * (1.0f / 16.0f) + tp / fmaxf(sqrtf(ns), 1e-12f);
}

// ---------------- launch ----------------
extern "C" void kernel_launch(void* const* d_in, const int* in_sizes, int n_in,
                              void* d_out, int out_size) {
    const float* Gu     = (const float*)d_in[0];
    const float* Gi     = (const float*)d_in[1];
    const float* Tu     = (const float*)d_in[2];
    const float* F      = (const float*)d_in[3];
    const float* proj_w = (const float*)d_in[4];
    const float* proj_b = (const float*)d_in[5];
    const int* ue       = (const int*)d_in[6];
    const int* ie       = (const int*)d_in[7];
    const int* users    = (const int*)d_in[8];
    const int* items    = (const int*)d_in[9];
    float* out          = (float*)d_out;

    const int n4blocks = ((NKF / 4) + 255) / 256;
    const int nnblocks = (NN + 255) / 256;
    const int neblocks = (NE + 255) / 256;
    const int gwblocks = (NN * 32 + 255) / 256;          // warp per node
    const int g3blocks = (2 * BATCHN * 32 + 255) / 256;  // warp per batch slot

    // CSR build
    k_zero_deg<<<nnblocks, 256>>>();
    k_count<<<neblocks, 256>>>(ue, ie);
    k_blocksum<<<NCHUNK, 1024>>>();
    k_scanbsum<<<1, 32>>>();
    k_localscan<<<NCHUNK, 1024>>>();
    k_fill<<<neblocks, 256>>>(ue, ie);

    // propagation: x0 -> x1 -> x2 (bf16 gathers), then batch-only layer 3
    k_init<<<n4blocks, 256>>>(Gu, Gi);
    k_gather<<<gwblocks, 256>>>(0);
    k_gather<<<gwblocks, 256>>>(1);
    k_gather3<<<g3blocks, 256>>>(Gu, Gi, users, items);

    // scoring
    k_proj_gemm<<<BATCHN / 64, 256>>>(F, proj_w, proj_b, items);
    k_score<<<(BATCHN * 32 + 255) / 256, 256>>>(Tu, users, out);
}